// round 1
// baseline (speedup 1.0000x reference)
#include <cuda_runtime.h>

#define NN 12288
#define EE 196608
#define FIN 1433
#define H1 32
#define H2 16
#define NC 7

// ---- scratch (static device globals; no allocation allowed) ----
__device__ float g_y[NN * H1];     // x @ W1
__device__ float g_acc[NN * H1];   // GCN edge accumulation
__device__ float g_h[NN * H1];     // GCN layer output
__device__ float g_sg[NN * H1];    // SAGE sum
__device__ int   g_deg[NN];
__device__ int   g_cnt[NN];
__device__ float g_dis[NN];
__device__ int   g_is64;

// ---- edge-index dtype detection (int64 requested by ref, but JAX w/o x64
// silently downgrades to int32; detect on device) ----
__global__ void k_detect(const int* ei32) {
    if (blockIdx.x == 0 && threadIdx.x == 0) {
        int all0 = 1;
        for (int k = 0; k < 64; k++) {
            if (ei32[2 * k + 1] != 0) { all0 = 0; break; }
        }
        g_is64 = all0;   // hi words all zero -> int64 layout
    }
}

__device__ __forceinline__ int eidx(const void* ei, int which, int e) {
    if (g_is64) return (int)(((const long long*)ei)[(long long)which * EE + e]);
    return ((const int*)ei)[which * EE + e];
}

__global__ void k_init() {
    int i = blockIdx.x * blockDim.x + threadIdx.x;
    if (i < NN * H1) { g_y[i] = 0.f; g_acc[i] = 0.f; g_sg[i] = 0.f; }
    if (i < NN)      { g_deg[i] = 1; g_cnt[i] = 0; }   // deg starts at 1 (self loop)
}

__global__ void k_count(const void* ei) {
    int e = blockIdx.x * blockDim.x + threadIdx.x;
    if (e < EE) {
        int s = eidx(ei, 0, e);
        int c = eidx(ei, 1, e);
        atomicAdd(&g_deg[c], 1);
        atomicAdd(&g_cnt[s], 1);
    }
}

__global__ void k_dis() {
    int i = blockIdx.x * blockDim.x + threadIdx.x;
    if (i < NN) g_dis[i] = rsqrtf((float)g_deg[i]);
}

// ---- GEMM: y = x @ W1,  [12288,1433] @ [1433,32] ----
// BM=128 rows/block, BK=32, 256 threads, 4x4 register tile, split-K=6.
#define BM 128
#define BK 32
#define KSPLIT 6

__global__ void __launch_bounds__(256) k_gemm1(const float* __restrict__ x,
                                               const float* __restrict__ W1) {
    __shared__ float xs[BM][BK + 1];   // +1 pad: conflict-free column reads
    __shared__ float ws[BK][H1];

    const int tid  = threadIdx.x;
    const int row0 = blockIdx.x * BM;
    const int kchunk = (FIN + KSPLIT - 1) / KSPLIT;
    const int kBegin = blockIdx.y * kchunk;
    const int kEnd   = min(kBegin + kchunk, FIN);

    const int tx = tid & 7;    // col group: cols tx*4 .. tx*4+3
    const int ty = tid >> 3;   // row group: rows ty*4 .. ty*4+3

    float acc[4][4] = {};

    for (int k0 = kBegin; k0 < kEnd; k0 += BK) {
        // load x tile [BM][BK], coalesced along k
        {
            const int kk = tid & 31;
            const int mb = tid >> 5;
            const int k  = k0 + kk;
            const bool kok = (k < kEnd);
            #pragma unroll
            for (int it = 0; it < 16; it++) {
                const int m = mb + it * 8;
                xs[m][kk] = kok ? x[(row0 + m) * FIN + k] : 0.f;
            }
        }
        // load W tile [BK][32]
        {
            const int c = tid & 31;
            #pragma unroll
            for (int it = 0; it < 4; it++) {
                const int kk = (tid >> 5) + it * 8;
                const int k  = k0 + kk;
                ws[kk][c] = (k < kEnd) ? W1[k * H1 + c] : 0.f;
            }
        }
        __syncthreads();

        #pragma unroll
        for (int kk = 0; kk < BK; kk++) {
            const float4 wv = *(const float4*)&ws[kk][tx * 4];
            #pragma unroll
            for (int j = 0; j < 4; j++) {
                const float xv = xs[ty * 4 + j][kk];
                acc[j][0] += xv * wv.x;
                acc[j][1] += xv * wv.y;
                acc[j][2] += xv * wv.z;
                acc[j][3] += xv * wv.w;
            }
        }
        __syncthreads();
    }

    #pragma unroll
    for (int j = 0; j < 4; j++) {
        const int r = row0 + ty * 4 + j;
        #pragma unroll
        for (int l = 0; l < 4; l++)
            atomicAdd(&g_y[r * H1 + tx * 4 + l], acc[j][l]);
    }
}

// ---- GCN edge aggregation: acc[row] += dis[col] * y[col]  (lane per (e,c)) ----
__global__ void k_gcn_agg(const void* ei) {
    int idx = blockIdx.x * blockDim.x + threadIdx.x;
    int e = idx >> 5, c = idx & 31;
    int r  = eidx(ei, 0, e);
    int cl = eidx(ei, 1, e);
    atomicAdd(&g_acc[r * H1 + c], g_dis[cl] * g_y[cl * H1 + c]);
}

// ---- h = relu(dis[i]*(acc + dis[i]*y) + b1) ----
__global__ void k_h(const float* __restrict__ b1) {
    int idx = blockIdx.x * blockDim.x + threadIdx.x;
    int i = idx >> 5, c = idx & 31;
    float d = g_dis[i];
    float v = d * (g_acc[idx] + d * g_y[idx]) + b1[c];
    g_h[idx] = fmaxf(v, 0.f);
}

// ---- SAGE aggregation: sg[src] += h[dst] ----
__global__ void k_sage_agg(const void* ei) {
    int idx = blockIdx.x * blockDim.x + threadIdx.x;
    int e = idx >> 5, c = idx & 31;
    int s = eidx(ei, 0, e);
    int d = eidx(ei, 1, e);
    atomicAdd(&g_sg[s * H1 + c], g_h[d * H1 + c]);
}

// ---- head: relu(h@Wl + bl + agg@Wr + br) -> L2 norm -> @W3+b3 -> softmax ----
__global__ void __launch_bounds__(256) k_head(const float* __restrict__ Wl,
                                              const float* __restrict__ bl,
                                              const float* __restrict__ Wr,
                                              const float* __restrict__ br,
                                              const float* __restrict__ W3,
                                              const float* __restrict__ b3,
                                              float* __restrict__ out) {
    __shared__ float sWl[H1 * H2], sWr[H1 * H2], sW3[H2 * NC];
    __shared__ float sbl[H2], sbr[H2], sb3[NC];
    const int tid = threadIdx.x;
    for (int i = tid; i < H1 * H2; i += blockDim.x) { sWl[i] = Wl[i]; sWr[i] = Wr[i]; }
    for (int i = tid; i < H2 * NC; i += blockDim.x) sW3[i] = W3[i];
    if (tid < H2) { sbl[tid] = bl[tid]; sbr[tid] = br[tid]; }
    if (tid < NC) sb3[tid] = b3[tid];
    __syncthreads();

    const int n = blockIdx.x * blockDim.x + tid;
    if (n >= NN) return;

    const float invc = 1.0f / fmaxf((float)g_cnt[n], 1.0f);

    float t[H2];
    #pragma unroll
    for (int j = 0; j < H2; j++) t[j] = sbl[j] + sbr[j];

    #pragma unroll 4
    for (int c = 0; c < H1; c++) {
        const float hv = g_h[n * H1 + c];
        const float av = g_sg[n * H1 + c] * invc;
        #pragma unroll
        for (int j = 0; j < H2; j++)
            t[j] += hv * sWl[c * H2 + j] + av * sWr[c * H2 + j];
    }

    float ss = 0.f;
    #pragma unroll
    for (int j = 0; j < H2; j++) { t[j] = fmaxf(t[j], 0.f); ss += t[j] * t[j]; }
    const float sc = 1.0f / (sqrtf(ss) + 1e-6f);

    float lg[NC];
    #pragma unroll
    for (int k = 0; k < NC; k++) lg[k] = sb3[k];
    #pragma unroll
    for (int j = 0; j < H2; j++) {
        const float tv = t[j] * sc;
        #pragma unroll
        for (int k = 0; k < NC; k++) lg[k] += tv * sW3[j * NC + k];
    }

    float mx = lg[0];
    #pragma unroll
    for (int k = 1; k < NC; k++) mx = fmaxf(mx, lg[k]);
    float se = 0.f;
    #pragma unroll
    for (int k = 0; k < NC; k++) { lg[k] = __expf(lg[k] - mx); se += lg[k]; }
    const float inv = 1.0f / se;
    #pragma unroll
    for (int k = 0; k < NC; k++) out[n * NC + k] = lg[k] * inv;
}

extern "C" void kernel_launch(void* const* d_in, const int* in_sizes, int n_in,
                              void* d_out, int out_size) {
    const float* x  = (const float*)d_in[0];
    const void*  ei = d_in[1];
    const float* W1 = (const float*)d_in[2];
    const float* b1 = (const float*)d_in[3];
    const float* Wl = (const float*)d_in[4];
    const float* bl = (const float*)d_in[5];
    const float* Wr = (const float*)d_in[6];
    const float* br = (const float*)d_in[7];
    const float* W3 = (const float*)d_in[8];
    const float* b3 = (const float*)d_in[9];
    float* out = (float*)d_out;

    k_detect<<<1, 32>>>((const int*)ei);
    k_init<<<(NN * H1 + 255) / 256, 256>>>();
    k_count<<<(EE + 255) / 256, 256>>>(ei);
    k_dis<<<(NN + 255) / 256, 256>>>();

    dim3 ggrid(NN / BM, KSPLIT);
    k_gemm1<<<ggrid, 256>>>(x, W1);

    k_gcn_agg<<<(EE * H1) / 256, 256>>>(ei);
    k_h<<<(NN * H1) / 256, 256>>>(b1);
    k_sage_agg<<<(EE * H1) / 256, 256>>>(ei);
    k_head<<<(NN + 255) / 256, 256>>>(Wl, bl, Wr, br, W3, b3, out);
}